// round 16
// baseline (speedup 1.0000x reference)
#include <cuda_runtime.h>
#include <math.h>

#define Bb 16
#define Hh 1024
#define Tt 4096
#define CD 8
#define CS 1024
#define HS 8            // H-splits for K1a
#define HC (Hh/HS)      // 128 h per block

static constexpr size_t OUT_N   = (size_t)Bb * Hh * Tt;          // 67108864
static constexpr size_t CL_OFF  = OUT_N;
static constexpr size_t CBL_OFF = OUT_N + 1;
static constexpr size_t IDX_OFF = OUT_N + 2;
static constexpr size_t PROJ_OFF = IDX_OFF + (size_t)Bb * Tt;
static constexpr size_t PROJ_N  = (size_t)Bb * CD * Tt;          // 524288

// packed-pair layout: per 4-token group (32 floats):
//   [ t0d0,t1d0, t0d1,t1d1, ... t0d7,t1d7,  t2d0,t3d0, ... t2d7,t3d7 ]
__device__ float g_pp[(size_t)HS * Bb * Tt * CD];  // 16.8MB
__device__ float g_partial[256];                   // per-block loss partials
__device__ int   g_done;                           // completion counter

// ---- packed f32x2 helpers ----
static __device__ __forceinline__ unsigned long long pk2(float lo, float hi) {
    unsigned long long r;
    asm("mov.b64 %0, {%1, %2};" : "=l"(r) : "f"(lo), "f"(hi));
    return r;
}
static __device__ __forceinline__ void upk2(unsigned long long v, float &lo, float &hi) {
    asm("mov.b64 {%0, %1}, %2;" : "=f"(lo), "=f"(hi) : "l"(v));
}
static __device__ __forceinline__ unsigned long long f2(unsigned long long a,
                                                        unsigned long long b,
                                                        unsigned long long c) {
    unsigned long long d;
    asm("fma.rn.f32x2 %0, %1, %2, %3;" : "=l"(d) : "l"(a), "l"(b), "l"(c));
    return d;
}
static __device__ __forceinline__ unsigned long long add2(unsigned long long a,
                                                          unsigned long long b) {
    unsigned long long d;
    asm("add.rn.f32x2 %0, %1, %2;" : "=l"(d) : "l"(a), "l"(b));
    return d;
}

// =====================================================================
// K1a: partial in-proj GEMV. (unchanged from R15; + g_done reset)
// grid 512 = b(16) x hs(8) x tc(4). block 256 threads, 4 tokens/thread.
// =====================================================================
__global__ void __launch_bounds__(256, 4) vq_k1a(
    const float* __restrict__ hidden,
    const float* __restrict__ w_in)
{
    __shared__ float wdup[HC * CD * 2];   // 8KB

    const int tid = threadIdx.x;
    const int blk = blockIdx.x;
    if (blk == 0 && tid == 0) g_done = 0;   // reset for vq_kf's last-block

    const int b   = blk >> 5;
    const int hs  = (blk >> 2) & 7;
    const int tc  = blk & 3;
    const int h0  = hs * HC;

    for (int i = tid; i < HC * CD; i += 256) {
        int h = i >> 3, d = i & 7;
        float w = w_in[(size_t)d * Hh + h0 + h];
        wdup[i * 2] = w; wdup[i * 2 + 1] = w;
    }
    __syncthreads();

    const int tbase = tc * 1024 + tid * 4;
    const float* hp = hidden + (size_t)b * Hh * Tt + (size_t)h0 * Tt + tbase;

    unsigned long long aA[8], aB[8];
#pragma unroll
    for (int d = 0; d < 8; d++) { aA[d] = 0ull; aB[d] = 0ull; }

#pragma unroll 8
    for (int h = 0; h < HC; h++) {
        ulonglong2 xv = *(const ulonglong2*)(hp + (size_t)h * Tt);
        unsigned long long xlo = xv.x;
        unsigned long long xhi = xv.y;
        ulonglong2 w01 = *(const ulonglong2*)(wdup + h * 16);
        ulonglong2 w23 = *(const ulonglong2*)(wdup + h * 16 + 4);
        ulonglong2 w45 = *(const ulonglong2*)(wdup + h * 16 + 8);
        ulonglong2 w67 = *(const ulonglong2*)(wdup + h * 16 + 12);
        aA[0] = f2(xlo, w01.x, aA[0]); aB[0] = f2(xhi, w01.x, aB[0]);
        aA[1] = f2(xlo, w01.y, aA[1]); aB[1] = f2(xhi, w01.y, aB[1]);
        aA[2] = f2(xlo, w23.x, aA[2]); aB[2] = f2(xhi, w23.x, aB[2]);
        aA[3] = f2(xlo, w23.y, aA[3]); aB[3] = f2(xhi, w23.y, aB[3]);
        aA[4] = f2(xlo, w45.x, aA[4]); aB[4] = f2(xhi, w45.x, aB[4]);
        aA[5] = f2(xlo, w45.y, aA[5]); aB[5] = f2(xhi, w45.y, aB[5]);
        aA[6] = f2(xlo, w67.x, aA[6]); aB[6] = f2(xhi, w67.x, aB[6]);
        aA[7] = f2(xlo, w67.y, aA[7]); aB[7] = f2(xhi, w67.y, aB[7]);
    }

    ulonglong2* pq = (ulonglong2*)(g_pp + (((size_t)hs * Bb + b) * Tt + tbase) * 8);
    ulonglong2 s;
    s.x = aA[0]; s.y = aA[1]; pq[0] = s;
    s.x = aA[2]; s.y = aA[3]; pq[1] = s;
    s.x = aA[4]; s.y = aA[5]; pq[2] = s;
    s.x = aA[6]; s.y = aA[7]; pq[3] = s;
    s.x = aB[0]; s.y = aB[1]; pq[4] = s;
    s.x = aB[2]; s.y = aB[3]; pq[5] = s;
    s.x = aB[4]; s.y = aB[5]; pq[6] = s;
    s.x = aB[6]; s.y = aB[7]; pq[7] = s;
}

// =====================================================================
// KF: fused reduce + NN + out-proj.
// grid 256 = b(16) x t-chunk(16 of 256 tokens), block 128 = 128 pairs.
// dyn smem floats:
//   cbpf [0,8192) | cseed [8192,9216) | wsm [9216,17408)
//   bsm [17408,18432) | inb [18432,18440) | red [18440,18568)
// =====================================================================
__global__ void __launch_bounds__(128) vq_kf(
    const float* __restrict__ b_in,
    const float* __restrict__ codebook,
    const float* __restrict__ w_out,
    const float* __restrict__ b_out,
    float* __restrict__ out)
{
    extern __shared__ float sm[];
    float* cbpf  = sm;
    float* cseed = sm + 8192;
    float* wsm   = sm + 9216;
    float* bsm   = sm + 17408;
    float* inb   = sm + 18432;
    float* red   = sm + 18440;

    const int tid = threadIdx.x;
    const int blk = blockIdx.x;
    const int b   = blk >> 4;
    const int t0c = (blk & 15) << 8;

    if (tid < 8) inb[tid] = b_in[tid];

    // stage w_out [1024][8] and bias
    for (int i = tid; i < 2048; i += 128)
        *(float4*)(wsm + i * 4) = __ldg((const float4*)(w_out + i * 4));
    for (int i = tid; i < 1024; i += 128)
        bsm[i] = b_out[i];

    // normalize codebook into pair-interleaved layout
    for (int j = tid; j < CS; j += 128) {
        float4 c0 = __ldg((const float4*)(codebook + j * 8));
        float4 c1 = __ldg((const float4*)(codebook + j * 8 + 4));
        float c[8] = { c0.x, c0.y, c0.z, c0.w, c1.x, c1.y, c1.z, c1.w };
        float n2 = 0.f;
#pragma unroll
        for (int d = 0; d < 8; d++) n2 = fmaf(c[d], c[d], n2);
        float r = 1.0f / fmaxf(sqrtf(n2), 1e-12f);
        float cn2 = 0.f;
#pragma unroll
        for (int d = 0; d < 8; d++) { c[d] *= r; cn2 = fmaf(c[d], c[d], cn2); }
        int p = j >> 1, o = j & 1;
#pragma unroll
        for (int d = 0; d < 8; d++) cbpf[p * 16 + d * 2 + o] = c[d];
        cseed[p * 2 + o] = 0.5f * cn2;
    }
    __syncthreads();

    const int t0 = t0c + tid * 2;            // even token of this pair

    // ---- reduce HS partials (deterministic fixed order) ----
    const size_t segoff = ((tid >> 1) * 32) + ((tid & 1) * 16);
    unsigned long long pacc[8];
#pragma unroll
    for (int d = 0; d < 8; d++) pacc[d] = 0ull;
#pragma unroll
    for (int hs = 0; hs < HS; hs++) {
        const float* base = g_pp + (((size_t)hs * Bb + b) * Tt + t0c) * 8 + segoff;
        ulonglong2 u0 = *(const ulonglong2*)(base);
        ulonglong2 u1 = *(const ulonglong2*)(base + 4);
        ulonglong2 u2 = *(const ulonglong2*)(base + 8);
        ulonglong2 u3 = *(const ulonglong2*)(base + 12);
        pacc[0] = add2(pacc[0], u0.x); pacc[1] = add2(pacc[1], u0.y);
        pacc[2] = add2(pacc[2], u1.x); pacc[3] = add2(pacc[3], u1.y);
        pacc[4] = add2(pacc[4], u2.x); pacc[5] = add2(pacc[5], u2.y);
        pacc[6] = add2(pacc[6], u3.x); pacc[7] = add2(pacc[7], u3.y);
    }
#pragma unroll
    for (int d = 0; d < 8; d++) pacc[d] = add2(pacc[d], pk2(inb[d], inb[d]));

#pragma unroll
    for (int d = 0; d < 8; d++) {
        float p0, p1; upk2(pacc[d], p0, p1);
        *(float2*)(out + PROJ_OFF + ((size_t)b * 8 + d) * Tt + t0) = make_float2(p0, p1);
    }

    // ---- NN search (pair-packed, unchanged math) ----
    unsigned long long n2p = 0ull;
#pragma unroll
    for (int d = 0; d < 8; d++) n2p = f2(pacc[d], pacc[d], n2p);
    float l20, l21; upk2(n2p, l20, l21);
    float rr0 = 1.0f / fmaxf(sqrtf(l20), 1e-12f);
    float rr1 = 1.0f / fmaxf(sqrtf(l21), 1e-12f);

    unsigned long long e0[8], e1[8];
#pragma unroll
    for (int d = 0; d < 8; d++) {
        float p0, p1; upk2(pacc[d], p0, p1);
        float a0 = p0 * rr0, a1 = p1 * rr1;
        e0[d] = pk2(a0, a0);
        e1[d] = pk2(a1, a1);
    }

    float best0 = -3.4e38f, best1 = -3.4e38f;
    int bi0 = 0, bi1 = 0;
#pragma unroll 2
    for (int p = 0; p < 512; p++) {
        unsigned long long seed = *(const unsigned long long*)(cseed + p * 2);
        ulonglong2 cA = *(const ulonglong2*)(cbpf + p * 16);
        ulonglong2 cB = *(const ulonglong2*)(cbpf + p * 16 + 4);
        ulonglong2 cC = *(const ulonglong2*)(cbpf + p * 16 + 8);
        ulonglong2 cD = *(const ulonglong2*)(cbpf + p * 16 + 12);
        unsigned long long xA = seed, xB = 0ull;   // token0
        unsigned long long yA = seed, yB = 0ull;   // token1
        xA = f2(e0[0], cA.x, xA); xB = f2(e0[1], cA.y, xB);
        yA = f2(e1[0], cA.x, yA); yB = f2(e1[1], cA.y, yB);
        xA = f2(e0[2], cB.x, xA); xB = f2(e0[3], cB.y, xB);
        yA = f2(e1[2], cB.x, yA); yB = f2(e1[3], cB.y, yB);
        xA = f2(e0[4], cC.x, xA); xB = f2(e0[5], cC.y, xB);
        yA = f2(e1[4], cC.x, yA); yB = f2(e1[5], cC.y, yB);
        xA = f2(e0[6], cD.x, xA); xB = f2(e0[7], cD.y, xB);
        yA = f2(e1[6], cD.x, yA); yB = f2(e1[7], cD.y, yB);
        unsigned long long ax = add2(xA, xB);
        unsigned long long ay = add2(yA, yB);
        float s0, s1; upk2(ax, s0, s1);
        if (s0 > best0) { best0 = s0; bi0 = 2 * p; }
        if (s1 > best0) { best0 = s1; bi0 = 2 * p + 1; }
        upk2(ay, s0, s1);
        if (s0 > best1) { best1 = s0; bi1 = 2 * p; }
        if (s1 > best1) { best1 = s1; bi1 = 2 * p + 1; }
    }

    float4 qa0 = __ldg((const float4*)(codebook + bi0 * 8));
    float4 qa1 = __ldg((const float4*)(codebook + bi0 * 8 + 4));
    float4 qb0 = __ldg((const float4*)(codebook + bi1 * 8));
    float4 qb1 = __ldg((const float4*)(codebook + bi1 * 8 + 4));
    float q0[8] = { qa0.x, qa0.y, qa0.z, qa0.w, qa1.x, qa1.y, qa1.z, qa1.w };
    float q1[8] = { qb0.x, qb0.y, qb0.z, qb0.w, qb1.x, qb1.y, qb1.z, qb1.w };

    float ls = 0.f;
    unsigned long long qp[8];   // packed {q_t0[d], q_t1[d]} kept in registers
#pragma unroll
    for (int d = 0; d < 8; d++) {
        float p0, p1; upk2(pacc[d], p0, p1);
        float d0 = p0 - q0[d], d1 = p1 - q1[d];
        ls = fmaf(d0, d0, ls); ls = fmaf(d1, d1, ls);
        qp[d] = pk2(q0[d], q1[d]);
    }
    *(float2*)(out + IDX_OFF + (size_t)b * Tt + t0) = make_float2((float)bi0, (float)bi1);

    red[tid] = ls;
    __syncthreads();
    for (int s = 64; s > 0; s >>= 1) {
        if (tid < s) red[tid] += red[tid + s];
        __syncthreads();
    }
    if (tid == 0) g_partial[blk] = red[0];

    // ---- out-proj: all 1024 h-rows from register-resident quant ----
    float* op = out + (size_t)b * Hh * Tt + t0;   // h=0 row, this pair's column
#pragma unroll 4
    for (int h = 0; h < Hh; h++) {
        float bh = bsm[h];
        unsigned long long acc = pk2(bh, bh);
        ulonglong2 wA = *(const ulonglong2*)(wsm + h * 8);
        ulonglong2 wB = *(const ulonglong2*)(wsm + h * 8 + 4);
        float w0, w1, w2, w3, w4, w5, w6, w7;
        upk2(wA.x, w0, w1); upk2(wA.y, w2, w3);
        upk2(wB.x, w4, w5); upk2(wB.y, w6, w7);
        acc = f2(qp[0], pk2(w0, w0), acc);
        acc = f2(qp[1], pk2(w1, w1), acc);
        acc = f2(qp[2], pk2(w2, w2), acc);
        acc = f2(qp[3], pk2(w3, w3), acc);
        acc = f2(qp[4], pk2(w4, w4), acc);
        acc = f2(qp[5], pk2(w5, w5), acc);
        acc = f2(qp[6], pk2(w6, w6), acc);
        acc = f2(qp[7], pk2(w7, w7), acc);
        float o0, o1; upk2(acc, o0, o1);
        *(float2*)(op + (size_t)h * Tt) = make_float2(o0, o1);
    }

    // ---- last block finalizes the losses ----
    __shared__ int sm_last;
    __threadfence();
    if (tid == 0) sm_last = (atomicAdd(&g_done, 1) == 255) ? 1 : 0;
    __syncthreads();
    if (sm_last) {
        double* sd = (double*)red;   // 128 doubles fit? red is 128 floats...
        // use a dedicated accumulation in registers instead (deterministic):
        if (tid == 0) {
            double acc = 0.0;
            for (int i = 0; i < 256; i++) acc += (double)g_partial[i];
            float loss = (float)(acc / (double)PROJ_N);
            out[CL_OFF]  = loss;
            out[CBL_OFF] = loss;
        }
        (void)sd;
    }
}

extern "C" void kernel_launch(void* const* d_in, const int* in_sizes, int n_in,
                              void* d_out, int out_size)
{
    const float* hidden = (const float*)d_in[0];
    const float* w_in   = (const float*)d_in[1];
    const float* b_in   = (const float*)d_in[2];
    const float* w_out  = (const float*)d_in[3];
    const float* b_out  = (const float*)d_in[4];
    const float* cb     = (const float*)d_in[5];
    float* out = (float*)d_out;

    const int smemf = 18568 * 4;   // 74272 B
    cudaFuncSetAttribute(vq_kf, cudaFuncAttributeMaxDynamicSharedMemorySize, smemf);

    vq_k1a<<<512, 256>>>(hidden, w_in);
    vq_kf<<<256, 128, smemf>>>(b_in, cb, w_out, b_out, out);
}